// round 10
// baseline (speedup 1.0000x reference)
#include <cuda_runtime.h>
#include <cuda_bf16.h>
#include <cstdint>

// Problem constants (fixed by setup_inputs)
#define BATCH 4
#define SEQ   2048
#define CDIM  1024
#define NHEAD 16
#define HDIM  64
#define MROWS (BATCH * SEQ)   // 8192
#define K3    (3 * CDIM)      // 3072 : [hi | hi | lo] x [hi | lo | hi]

// Scratch (allocation-free: __device__ globals)
__device__ __nv_bfloat16 g_A3[MROWS * K3];   // split-expanded x
__device__ __nv_bfloat16 g_Y3[MROWS * K3];   // split-expanded attention output
__device__ __nv_bfloat16 g_W3q[CDIM * K3];
__device__ __nv_bfloat16 g_W3k[CDIM * K3];
__device__ __nv_bfloat16 g_W3v[CDIM * K3];
__device__ __nv_bfloat16 g_W3p[CDIM * K3];

// bf16 hi/lo split Q,K in [B,H,T,D]; V transposed in [B,H,D,T]
__device__ __nv_bfloat16 g_Qhi[BATCH * NHEAD * SEQ * HDIM];
__device__ __nv_bfloat16 g_Qlo[BATCH * NHEAD * SEQ * HDIM];
__device__ __nv_bfloat16 g_Khi[BATCH * NHEAD * SEQ * HDIM];
__device__ __nv_bfloat16 g_Klo[BATCH * NHEAD * SEQ * HDIM];
__device__ __nv_bfloat16 g_VThi[BATCH * NHEAD * HDIM * SEQ];
__device__ __nv_bfloat16 g_VTlo[BATCH * NHEAD * HDIM * SEQ];

// ---------------------------------------------------------------------------
// Split-convert: fp32 [rows,1024] -> bf16 [rows,3072].
// modeA=1: [hi | hi | lo] (activations), modeA=0: [hi | lo | hi] (weights)
// ---------------------------------------------------------------------------
__global__ __launch_bounds__(256)
void cvt_split3(const float* __restrict__ src, __nv_bfloat16* __restrict__ dst,
                int total, int modeA)
{
    int idx = blockIdx.x * 256 + threadIdx.x;
    if (idx >= total) return;
    int r = idx >> 10;
    int k = idx & 1023;
    float a = src[idx];
    __nv_bfloat16 hi = __float2bfloat16(a);
    __nv_bfloat16 lo = __float2bfloat16(a - __bfloat162float(hi));
    __nv_bfloat16* row = dst + (size_t)r * K3;
    if (modeA) {
        row[k]        = hi;
        row[k + 1024] = hi;
        row[k + 2048] = lo;
    } else {
        row[k]        = hi;
        row[k + 1024] = lo;
        row[k + 2048] = hi;
    }
}

// ---------------------------------------------------------------------------
// mma.sync m16n8k16 bf16 -> fp32 and ldmatrix helpers
// ---------------------------------------------------------------------------
__device__ __forceinline__ void mma16816(float* d, const uint32_t* a, const uint32_t* b)
{
    asm volatile(
        "mma.sync.aligned.m16n8k16.row.col.f32.bf16.bf16.f32 "
        "{%0,%1,%2,%3}, {%4,%5,%6,%7}, {%8,%9}, {%0,%1,%2,%3};"
        : "+f"(d[0]), "+f"(d[1]), "+f"(d[2]), "+f"(d[3])
        : "r"(a[0]), "r"(a[1]), "r"(a[2]), "r"(a[3]),
          "r"(b[0]), "r"(b[1]));
}

__device__ __forceinline__ void ldsm4(uint32_t* r, uint32_t saddr)
{
    asm volatile(
        "ldmatrix.sync.aligned.m8n8.x4.shared.b16 {%0,%1,%2,%3}, [%4];"
        : "=r"(r[0]), "=r"(r[1]), "=r"(r[2]), "=r"(r[3])
        : "r"(saddr));
}

__device__ __forceinline__ void hilo2(float a, float b, uint32_t& hi, uint32_t& lo)
{
    __nv_bfloat16 ha = __float2bfloat16(a);
    __nv_bfloat16 hb = __float2bfloat16(b);
    __nv_bfloat16 la = __float2bfloat16(a - __bfloat162float(ha));
    __nv_bfloat16 lb = __float2bfloat16(b - __bfloat162float(hb));
    __nv_bfloat162 hh; hh.x = ha; hh.y = hb;
    __nv_bfloat162 ll; ll.x = la; ll.y = lb;
    hi = *(uint32_t*)&hh;
    lo = *(uint32_t*)&ll;
}

// ---------------------------------------------------------------------------
// bf16 tensor-core GEMM: out[M,1024] = A3[M,3072] @ W3[1024,3072]^T + bias.
// mode 0: bf16 hi/lo split-heads [B,H,T,D] (Q/K)
// mode 2: bf16 hi/lo transposed heads [B,H,D,T] (V)
// mode 1: fp32 plain [M,N] (final output)
// ---------------------------------------------------------------------------
#define SMPAD 40   // padded row length in bf16 elements

__global__ __launch_bounds__(256)
void gemm_bf16_mma(const __nv_bfloat16* __restrict__ A,
                   const __nv_bfloat16* __restrict__ W,
                   const float* __restrict__ bias,
                   float* __restrict__ outF,
                   __nv_bfloat16* __restrict__ outH,
                   __nv_bfloat16* __restrict__ outL,
                   int mode)
{
    __shared__ __nv_bfloat16 As[128][SMPAD];
    __shared__ __nv_bfloat16 Ws[128][SMPAD];

    const int tid  = threadIdx.x;
    const int bm   = blockIdx.y * 128;
    const int bn   = blockIdx.x * 128;
    const int warp = tid >> 5;
    const int lane = tid & 31;
    const int wm   = (warp >> 2) * 64;
    const int wn   = (warp & 3) * 32;
    const int g    = lane >> 2;
    const int c    = lane & 3;

    const int r0 = tid >> 2,         q0 = tid & 3;
    const int r1 = (tid + 256) >> 2, q1 = (tid + 256) & 3;

    const __nv_bfloat16* Ag0 = A + (size_t)(bm + r0) * K3 + q0 * 8;
    const __nv_bfloat16* Ag1 = A + (size_t)(bm + r1) * K3 + q1 * 8;
    const __nv_bfloat16* Wg0 = W + (size_t)(bn + r0) * K3 + q0 * 8;
    const __nv_bfloat16* Wg1 = W + (size_t)(bn + r1) * K3 + q1 * 8;

    float acc[4][4][4];
#pragma unroll
    for (int i = 0; i < 4; i++)
#pragma unroll
        for (int j = 0; j < 4; j++)
#pragma unroll
            for (int e = 0; e < 4; e++) acc[i][j][e] = 0.0f;

    uint4 pa0 = *(const uint4*)(Ag0);
    uint4 pa1 = *(const uint4*)(Ag1);
    uint4 pw0 = *(const uint4*)(Wg0);
    uint4 pw1 = *(const uint4*)(Wg1);

    for (int k0 = 0; k0 < K3; k0 += 32) {
        *(uint4*)&As[r0][q0 * 8] = pa0;
        *(uint4*)&As[r1][q1 * 8] = pa1;
        *(uint4*)&Ws[r0][q0 * 8] = pw0;
        *(uint4*)&Ws[r1][q1 * 8] = pw1;
        __syncthreads();

        if (k0 + 32 < K3) {
            pa0 = *(const uint4*)(Ag0 + k0 + 32);
            pa1 = *(const uint4*)(Ag1 + k0 + 32);
            pw0 = *(const uint4*)(Wg0 + k0 + 32);
            pw1 = *(const uint4*)(Wg1 + k0 + 32);
        }

#pragma unroll
        for (int kk = 0; kk < 2; kk++) {
            const int kb = kk * 16;
            uint32_t af[4][4];
#pragma unroll
            for (int mf = 0; mf < 4; mf++) {
                const int mr = wm + mf * 16 + g;
                af[mf][0] = *(const uint32_t*)&As[mr    ][kb + 2 * c];
                af[mf][1] = *(const uint32_t*)&As[mr + 8][kb + 2 * c];
                af[mf][2] = *(const uint32_t*)&As[mr    ][kb + 2 * c + 8];
                af[mf][3] = *(const uint32_t*)&As[mr + 8][kb + 2 * c + 8];
            }
            uint32_t bf[4][2];
#pragma unroll
            for (int nf = 0; nf < 4; nf++) {
                const int nr = wn + nf * 8 + g;
                bf[nf][0] = *(const uint32_t*)&Ws[nr][kb + 2 * c];
                bf[nf][1] = *(const uint32_t*)&Ws[nr][kb + 2 * c + 8];
            }
#pragma unroll
            for (int mf = 0; mf < 4; mf++)
#pragma unroll
                for (int nf = 0; nf < 4; nf++)
                    mma16816(acc[mf][nf], af[mf], bf[nf]);
        }
        __syncthreads();
    }

#pragma unroll
    for (int nf = 0; nf < 4; nf++) {
        const int col = bn + wn + nf * 8 + 2 * c;
        const float b0 = bias[col];
        const float b1 = bias[col + 1];
#pragma unroll
        for (int mf = 0; mf < 4; mf++) {
            const int row = bm + wm + mf * 16 + g;
            const float v00 = acc[mf][nf][0] + b0;
            const float v01 = acc[mf][nf][1] + b1;
            const float v10 = acc[mf][nf][2] + b0;
            const float v11 = acc[mf][nf][3] + b1;
            if (mode == 1) {
                *(float2*)(outF + (size_t)row * CDIM + col)       = make_float2(v00, v01);
                *(float2*)(outF + (size_t)(row + 8) * CDIM + col) = make_float2(v10, v11);
            } else {
                const int h  = col >> 6;
                const int d  = col & (HDIM - 1);
                const int b_ = row >> 11;
                const int t0 = row & (SEQ - 1);
                const int t1 = (row + 8) & (SEQ - 1);
                uint32_t h0, l0, h1, l1;
                hilo2(v00, v01, h0, l0);
                hilo2(v10, v11, h1, l1);
                if (mode == 0) {
                    // [B,H,T,D]
                    const size_t i0 = ((size_t)(b_ * NHEAD + h) * SEQ + t0) * HDIM + d;
                    const size_t i1 = ((size_t)(b_ * NHEAD + h) * SEQ + t1) * HDIM + d;
                    *(uint32_t*)&outH[i0] = h0;
                    *(uint32_t*)&outL[i0] = l0;
                    *(uint32_t*)&outH[i1] = h1;
                    *(uint32_t*)&outL[i1] = l1;
                } else {
                    // mode 2: [B,H,D,T] (transposed V)
                    const size_t base = ((size_t)(b_ * NHEAD + h) * HDIM + d) * SEQ;
                    __nv_bfloat162 hh0 = *(__nv_bfloat162*)&h0;
                    __nv_bfloat162 ll0 = *(__nv_bfloat162*)&l0;
                    __nv_bfloat162 hh1 = *(__nv_bfloat162*)&h1;
                    __nv_bfloat162 ll1 = *(__nv_bfloat162*)&l1;
                    outH[base + t0]       = hh0.x;
                    outH[base + SEQ + t0] = hh0.y;
                    outH[base + t1]       = hh1.x;
                    outH[base + SEQ + t1] = hh1.y;
                    outL[base + t0]       = ll0.x;
                    outL[base + SEQ + t0] = ll0.y;
                    outL[base + t1]       = ll1.x;
                    outL[base + SEQ + t1] = ll1.y;
                }
            }
        }
    }
}

// ---------------------------------------------------------------------------
// Flash attention (causal) on tensor cores with 3-term bf16 compensation.
// BQ=128, BK=64, 8 warps; warp w owns q-rows [16w,16w+16) exclusively.
// Fragment loads via ldmatrix.x4 (AST=72 -> 4-bank row stride, conflict-free).
// ---------------------------------------------------------------------------
#define AST 72   // padded smem row stride (bf16 elems); 36 banks == 4 mod 32
#define ATT_SMEM_BYTES ((2 * 128 * AST + 4 * 64 * AST) * 2)   // 73728 B

__global__ __launch_bounds__(256)
void flash_attn_mma(__nv_bfloat16* __restrict__ Y3)
{
    extern __shared__ __nv_bfloat16 smem[];
    __nv_bfloat16* Qh = smem;                 // 128 x AST
    __nv_bfloat16* Ql = Qh + 128 * AST;
    __nv_bfloat16* Kh = Ql + 128 * AST;       // 64 x AST
    __nv_bfloat16* Kl = Kh + 64 * AST;
    __nv_bfloat16* Vh = Kl + 64 * AST;        // VT: 64 x AST
    __nv_bfloat16* Vl = Vh + 64 * AST;

    const int qt  = blockIdx.x;   // 0..15
    const int h   = blockIdx.y;
    const int b   = blockIdx.z;
    const int tid = threadIdx.x;
    const int warp = tid >> 5;
    const int lane = tid & 31;
    const int g    = lane >> 2;
    const int c    = lane & 3;
    const int qrl  = warp * 16;               // local q-row base of this warp

    // ldmatrix per-lane address components
    const int rL = lane & 7;
    const int mL = lane >> 3;
    const int aRow = ((mL & 1) << 3) + rL;    // A-frag: m0,m2 rows 0-7; m1,m3 rows 8-15
    const int aCol = (mL >> 1) << 3;          // A-frag: m0,m1 cols 0-7; m2,m3 cols 8-15
    const int bRow = ((mL >> 1) << 3) + rL;   // B-frag: m0,m1 rows 0-7; m2,m3 rows 8-15
    const int bCol = (mL & 1) << 3;           // B-frag: m0,m2 cols 0-7; m1,m3 cols 8-15

    const uint32_t qh_s = (uint32_t)__cvta_generic_to_shared(Qh);
    const uint32_t ql_s = (uint32_t)__cvta_generic_to_shared(Ql);
    const uint32_t kh_s = (uint32_t)__cvta_generic_to_shared(Kh);
    const uint32_t kl_s = (uint32_t)__cvta_generic_to_shared(Kl);
    const uint32_t vh_s = (uint32_t)__cvta_generic_to_shared(Vh);
    const uint32_t vl_s = (uint32_t)__cvta_generic_to_shared(Vl);

    const size_t headBase = (size_t)(b * NHEAD + h) * SEQ * HDIM;
    const __nv_bfloat16* qh_g = g_Qhi + headBase + (size_t)qt * 128 * HDIM;
    const __nv_bfloat16* ql_g = g_Qlo + headBase + (size_t)qt * 128 * HDIM;
    const __nv_bfloat16* kh_g = g_Khi + headBase;
    const __nv_bfloat16* kl_g = g_Klo + headBase;
    const __nv_bfloat16* vh_g = g_VThi + headBase;   // [D,T] within head
    const __nv_bfloat16* vl_g = g_VTlo + headBase;

    // Load Q tile (128 x 64 hi + lo)
    {
        const int row = tid >> 1;
        const int d0  = (tid & 1) * 32;
#pragma unroll
        for (int i = 0; i < 4; i++) {
            *(uint4*)&Qh[row * AST + d0 + i * 8] =
                *(const uint4*)(qh_g + (size_t)row * HDIM + d0 + i * 8);
            *(uint4*)&Ql[row * AST + d0 + i * 8] =
                *(const uint4*)(ql_g + (size_t)row * HDIM + d0 + i * 8);
        }
    }

    float oacc[8][4];
#pragma unroll
    for (int n = 0; n < 8; n++)
#pragma unroll
        for (int e = 0; e < 4; e++) oacc[n][e] = 0.0f;

    float m0 = -1e30f, m1 = -1e30f, l0 = 0.0f, l1 = 0.0f;
    const float SC = 0.125f;   // 1/sqrt(64)
    const int tw = qt * 128 + qrl;           // global first row of warp
    const int warpRowMax = tw + 15;
    const int jtEnd = 2 * qt + 1;

    for (int jt = 0; jt <= jtEnd; jt++) {
        __syncthreads();
        // Load K (hi/lo) [64 x 64] and VT (hi/lo) [64 x 64]
        {
            const int j  = tid >> 2;
            const int d8 = (tid & 3) * 16;
            const size_t kg = (size_t)(jt * 64 + j) * HDIM;
            *(uint4*)&Kh[j * AST + d8]     = *(const uint4*)(kh_g + kg + d8);
            *(uint4*)&Kh[j * AST + d8 + 8] = *(const uint4*)(kh_g + kg + d8 + 8);
            *(uint4*)&Kl[j * AST + d8]     = *(const uint4*)(kl_g + kg + d8);
            *(uint4*)&Kl[j * AST + d8 + 8] = *(const uint4*)(kl_g + kg + d8 + 8);
            const size_t vg = (size_t)j * SEQ + jt * 64;   // row j = channel d here
            *(uint4*)&Vh[j * AST + d8]     = *(const uint4*)(vh_g + vg + d8);
            *(uint4*)&Vh[j * AST + d8 + 8] = *(const uint4*)(vh_g + vg + d8 + 8);
            *(uint4*)&Vl[j * AST + d8]     = *(const uint4*)(vl_g + vg + d8);
            *(uint4*)&Vl[j * AST + d8 + 8] = *(const uint4*)(vl_g + vg + d8 + 8);
        }
        __syncthreads();

        if (jt * 64 > warpRowMax) continue;   // fully masked for this warp

        // ----- S = Q K^T (3-term), fragments via ldmatrix -----
        float sacc[8][4];
#pragma unroll
        for (int n = 0; n < 8; n++)
#pragma unroll
            for (int e = 0; e < 4; e++) sacc[n][e] = 0.0f;

#pragma unroll
        for (int s = 0; s < 4; s++) {
            const int kb = s * 16;
            uint32_t qhf[4], qlf[4];
            ldsm4(qhf, qh_s + ((qrl + aRow) * AST + kb + aCol) * 2);
            ldsm4(qlf, ql_s + ((qrl + aRow) * AST + kb + aCol) * 2);
#pragma unroll
            for (int p = 0; p < 4; p++) {
                uint32_t bh[4], bl[4];   // {b[2p][0], b[2p][1], b[2p+1][0], b[2p+1][1]}
                ldsm4(bh, kh_s + ((p * 16 + bRow) * AST + kb + bCol) * 2);
                ldsm4(bl, kl_s + ((p * 16 + bRow) * AST + kb + bCol) * 2);
                mma16816(sacc[2 * p],     qhf, bh);
                mma16816(sacc[2 * p],     qhf, bl);
                mma16816(sacc[2 * p],     qlf, bh);
                mma16816(sacc[2 * p + 1], qhf, bh + 2);
                mma16816(sacc[2 * p + 1], qhf, bl + 2);
                mma16816(sacc[2 * p + 1], qlf, bh + 2);
            }
        }

        // ----- causal mask (diagonal tiles only) -----
        if (jt * 64 + 63 > tw) {
            const int r0g = tw + g;
            const int r1g = tw + g + 8;
#pragma unroll
            for (int n = 0; n < 8; n++) {
                const int col = jt * 64 + n * 8 + 2 * c;
                if (col     > r0g) sacc[n][0] = -1e30f;
                if (col + 1 > r0g) sacc[n][1] = -1e30f;
                if (col     > r1g) sacc[n][2] = -1e30f;
                if (col + 1 > r1g) sacc[n][3] = -1e30f;
            }
        }

        // ----- online softmax (rows g, g+8; raw-scale max tracking) -----
        float mx0 = -1e30f, mx1 = -1e30f;
#pragma unroll
        for (int n = 0; n < 8; n++) {
            mx0 = fmaxf(mx0, fmaxf(sacc[n][0], sacc[n][1]));
            mx1 = fmaxf(mx1, fmaxf(sacc[n][2], sacc[n][3]));
        }
        mx0 = fmaxf(mx0, __shfl_xor_sync(0xffffffffu, mx0, 1));
        mx0 = fmaxf(mx0, __shfl_xor_sync(0xffffffffu, mx0, 2));
        mx1 = fmaxf(mx1, __shfl_xor_sync(0xffffffffu, mx1, 1));
        mx1 = fmaxf(mx1, __shfl_xor_sync(0xffffffffu, mx1, 2));

        const float m0n = fmaxf(m0, mx0);
        const float m1n = fmaxf(m1, mx1);
        const float corr0 = __expf((m0 - m0n) * SC);
        const float corr1 = __expf((m1 - m1n) * SC);

        float sum0 = 0.0f, sum1 = 0.0f;
#pragma unroll
        for (int n = 0; n < 8; n++) {
            sacc[n][0] = __expf((sacc[n][0] - m0n) * SC);
            sacc[n][1] = __expf((sacc[n][1] - m0n) * SC);
            sacc[n][2] = __expf((sacc[n][2] - m1n) * SC);
            sacc[n][3] = __expf((sacc[n][3] - m1n) * SC);
            sum0 += sacc[n][0] + sacc[n][1];
            sum1 += sacc[n][2] + sacc[n][3];
        }
        sum0 += __shfl_xor_sync(0xffffffffu, sum0, 1);
        sum0 += __shfl_xor_sync(0xffffffffu, sum0, 2);
        sum1 += __shfl_xor_sync(0xffffffffu, sum1, 1);
        sum1 += __shfl_xor_sync(0xffffffffu, sum1, 2);

        l0 = l0 * corr0 + sum0;
        l1 = l1 * corr1 + sum1;
        m0 = m0n;
        m1 = m1n;

#pragma unroll
        for (int n = 0; n < 8; n++) {
            oacc[n][0] *= corr0;
            oacc[n][1] *= corr0;
            oacc[n][2] *= corr1;
            oacc[n][3] *= corr1;
        }

        // ----- O += P V (3-term); P frags from S accumulators -----
#pragma unroll
        for (int s = 0; s < 4; s++) {
            const int kb = s * 16;
            uint32_t ah[4], al[4];
            hilo2(sacc[2 * s][0],     sacc[2 * s][1],     ah[0], al[0]);
            hilo2(sacc[2 * s][2],     sacc[2 * s][3],     ah[1], al[1]);
            hilo2(sacc[2 * s + 1][0], sacc[2 * s + 1][1], ah[2], al[2]);
            hilo2(sacc[2 * s + 1][2], sacc[2 * s + 1][3], ah[3], al[3]);
#pragma unroll
            for (int p = 0; p < 4; p++) {
                uint32_t bh[4], bl[4];
                ldsm4(bh, vh_s + ((p * 16 + bRow) * AST + kb + bCol) * 2);
                ldsm4(bl, vl_s + ((p * 16 + bRow) * AST + kb + bCol) * 2);
                mma16816(oacc[2 * p],     ah, bh);
                mma16816(oacc[2 * p],     ah, bl);
                mma16816(oacc[2 * p],     al, bh);
                mma16816(oacc[2 * p + 1], ah, bh + 2);
                mma16816(oacc[2 * p + 1], ah, bl + 2);
                mma16816(oacc[2 * p + 1], al, bh + 2);
            }
        }
    }

    // ----- epilogue: normalize, write split-expanded Y3 [hi|hi|lo] -----
    const float inv0 = 1.0f / l0;
    const float inv1 = 1.0f / l1;
    const int t0 = qt * 128 + qrl + g;
    const int t1 = t0 + 8;
    const size_t r0 = (size_t)(b * SEQ + t0) * K3;
    const size_t r1 = (size_t)(b * SEQ + t1) * K3;
    const int ch = h * HDIM;
#pragma unroll
    for (int n = 0; n < 8; n++) {
        const int col = ch + n * 8 + 2 * c;
        uint32_t h0, l0p, h1, l1p;
        hilo2(oacc[n][0] * inv0, oacc[n][1] * inv0, h0, l0p);
        hilo2(oacc[n][2] * inv1, oacc[n][3] * inv1, h1, l1p);
        *(uint32_t*)&Y3[r0 + col]        = h0;
        *(uint32_t*)&Y3[r0 + 1024 + col] = h0;
        *(uint32_t*)&Y3[r0 + 2048 + col] = l0p;
        *(uint32_t*)&Y3[r1 + col]        = h1;
        *(uint32_t*)&Y3[r1 + 1024 + col] = h1;
        *(uint32_t*)&Y3[r1 + 2048 + col] = l1p;
    }
}

// ---------------------------------------------------------------------------
// Launch
// ---------------------------------------------------------------------------
extern "C" void kernel_launch(void* const* d_in, const int* in_sizes, int n_in,
                              void* d_out, int out_size)
{
    const float* x  = (const float*)d_in[0];
    const float* Wq = (const float*)d_in[1];
    const float* bq = (const float*)d_in[2];
    const float* Wk = (const float*)d_in[3];
    const float* bk = (const float*)d_in[4];
    const float* Wv = (const float*)d_in[5];
    const float* bv = (const float*)d_in[6];
    const float* Wp = (const float*)d_in[7];
    const float* bp = (const float*)d_in[8];

    __nv_bfloat16 *A3p, *Y3p, *W3qp, *W3kp, *W3vp, *W3pp;
    __nv_bfloat16 *Qhip, *Qlop, *Khip, *Klop, *VThip, *VTlop;
    cudaGetSymbolAddress((void**)&A3p, g_A3);
    cudaGetSymbolAddress((void**)&Y3p, g_Y3);
    cudaGetSymbolAddress((void**)&W3qp, g_W3q);
    cudaGetSymbolAddress((void**)&W3kp, g_W3k);
    cudaGetSymbolAddress((void**)&W3vp, g_W3v);
    cudaGetSymbolAddress((void**)&W3pp, g_W3p);
    cudaGetSymbolAddress((void**)&Qhip, g_Qhi);
    cudaGetSymbolAddress((void**)&Qlop, g_Qlo);
    cudaGetSymbolAddress((void**)&Khip, g_Khi);
    cudaGetSymbolAddress((void**)&Klop, g_Klo);
    cudaGetSymbolAddress((void**)&VThip, g_VThi);
    cudaGetSymbolAddress((void**)&VTlop, g_VTlo);

    cudaFuncSetAttribute(flash_attn_mma,
                         cudaFuncAttributeMaxDynamicSharedMemorySize,
                         ATT_SMEM_BYTES);

    const int actTotal = MROWS * CDIM;
    const int wTotal   = CDIM * CDIM;
    cvt_split3<<<(actTotal + 255) / 256, 256>>>(x, A3p, actTotal, 1);
    cvt_split3<<<(wTotal + 255) / 256, 256>>>(Wq, W3qp, wTotal, 0);
    cvt_split3<<<(wTotal + 255) / 256, 256>>>(Wk, W3kp, wTotal, 0);
    cvt_split3<<<(wTotal + 255) / 256, 256>>>(Wv, W3vp, wTotal, 0);
    cvt_split3<<<(wTotal + 255) / 256, 256>>>(Wp, W3pp, wTotal, 0);

    dim3 gemmGrid(CDIM / 128, MROWS / 128);   // (8, 64)
    gemm_bf16_mma<<<gemmGrid, 256>>>(A3p, W3qp, bq, nullptr, Qhip, Qlop, 0);
    gemm_bf16_mma<<<gemmGrid, 256>>>(A3p, W3kp, bk, nullptr, Khip, Klop, 0);
    gemm_bf16_mma<<<gemmGrid, 256>>>(A3p, W3vp, bv, nullptr, VThip, VTlop, 2);

    dim3 attnGrid(SEQ / 128, NHEAD, BATCH);   // (16, 16, 4)
    flash_attn_mma<<<attnGrid, 256, ATT_SMEM_BYTES>>>(Y3p);

    gemm_bf16_mma<<<gemmGrid, 256>>>(Y3p, W3pp, bp, (float*)d_out, nullptr, nullptr, 1);
}

// round 13
// speedup vs baseline: 1.0334x; 1.0334x over previous
#include <cuda_runtime.h>
#include <cuda_bf16.h>
#include <cstdint>

// Problem constants (fixed by setup_inputs)
#define BATCH 4
#define SEQ   2048
#define CDIM  1024
#define NHEAD 16
#define HDIM  64
#define MROWS (BATCH * SEQ)   // 8192
#define K3    (3 * CDIM)      // 3072 : [hi | hi | lo] x [hi | lo | hi]

// Scratch (allocation-free: __device__ globals)
__device__ __nv_bfloat16 g_A3[MROWS * K3];   // split-expanded x
__device__ __nv_bfloat16 g_Y3[MROWS * K3];   // split-expanded attention output
__device__ __nv_bfloat16 g_W3q[CDIM * K3];
__device__ __nv_bfloat16 g_W3k[CDIM * K3];
__device__ __nv_bfloat16 g_W3v[CDIM * K3];
__device__ __nv_bfloat16 g_W3p[CDIM * K3];

// bf16 hi/lo split Q,K in [B,H,T,D]; V transposed in [B,H,D,T]
__device__ __nv_bfloat16 g_Qhi[BATCH * NHEAD * SEQ * HDIM];
__device__ __nv_bfloat16 g_Qlo[BATCH * NHEAD * SEQ * HDIM];
__device__ __nv_bfloat16 g_Khi[BATCH * NHEAD * SEQ * HDIM];
__device__ __nv_bfloat16 g_Klo[BATCH * NHEAD * SEQ * HDIM];
__device__ __nv_bfloat16 g_VThi[BATCH * NHEAD * HDIM * SEQ];
__device__ __nv_bfloat16 g_VTlo[BATCH * NHEAD * HDIM * SEQ];

// ---------------------------------------------------------------------------
// Split-convert: fp32 [rows,1024] -> bf16 [rows,3072].
// modeA=1: [hi | hi | lo] (activations), modeA=0: [hi | lo | hi] (weights)
// ---------------------------------------------------------------------------
__global__ __launch_bounds__(256)
void cvt_split3(const float* __restrict__ src, __nv_bfloat16* __restrict__ dst,
                int total, int modeA)
{
    int idx = blockIdx.x * 256 + threadIdx.x;
    if (idx >= total) return;
    int r = idx >> 10;
    int k = idx & 1023;
    float a = src[idx];
    __nv_bfloat16 hi = __float2bfloat16(a);
    __nv_bfloat16 lo = __float2bfloat16(a - __bfloat162float(hi));
    __nv_bfloat16* row = dst + (size_t)r * K3;
    if (modeA) {
        row[k]        = hi;
        row[k + 1024] = hi;
        row[k + 2048] = lo;
    } else {
        row[k]        = hi;
        row[k + 1024] = lo;
        row[k + 2048] = hi;
    }
}

// ---------------------------------------------------------------------------
// mma.sync m16n8k16 bf16 -> fp32, ldmatrix, cp.async helpers
// ---------------------------------------------------------------------------
__device__ __forceinline__ void mma16816(float* d, const uint32_t* a, const uint32_t* b)
{
    asm volatile(
        "mma.sync.aligned.m16n8k16.row.col.f32.bf16.bf16.f32 "
        "{%0,%1,%2,%3}, {%4,%5,%6,%7}, {%8,%9}, {%0,%1,%2,%3};"
        : "+f"(d[0]), "+f"(d[1]), "+f"(d[2]), "+f"(d[3])
        : "r"(a[0]), "r"(a[1]), "r"(a[2]), "r"(a[3]),
          "r"(b[0]), "r"(b[1]));
}

__device__ __forceinline__ void ldsm4(uint32_t* r, uint32_t saddr)
{
    asm volatile(
        "ldmatrix.sync.aligned.m8n8.x4.shared.b16 {%0,%1,%2,%3}, [%4];"
        : "=r"(r[0]), "=r"(r[1]), "=r"(r[2]), "=r"(r[3])
        : "r"(saddr));
}

#define CP16(dst, src) \
    asm volatile("cp.async.cg.shared.global [%0], [%1], 16;" :: "r"(dst), "l"(src))
#define CP_COMMIT() asm volatile("cp.async.commit_group;")
#define CP_WAIT1()  asm volatile("cp.async.wait_group 1;")

__device__ __forceinline__ void hilo2(float a, float b, uint32_t& hi, uint32_t& lo)
{
    __nv_bfloat16 ha = __float2bfloat16(a);
    __nv_bfloat16 hb = __float2bfloat16(b);
    __nv_bfloat16 la = __float2bfloat16(a - __bfloat162float(ha));
    __nv_bfloat16 lb = __float2bfloat16(b - __bfloat162float(hb));
    __nv_bfloat162 hh; hh.x = ha; hh.y = hb;
    __nv_bfloat162 ll; ll.x = la; ll.y = lb;
    hi = *(uint32_t*)&hh;
    lo = *(uint32_t*)&ll;
}

// ---------------------------------------------------------------------------
// bf16 tensor-core GEMM: out[M,1024] = A3[M,3072] @ W3[1024,3072]^T + bias.
// mode 0: bf16 hi/lo split-heads [B,H,T,D] (Q/K)
// mode 2: bf16 hi/lo transposed heads [B,H,D,T] (V)
// mode 1: fp32 plain [M,N] (final output)
// ---------------------------------------------------------------------------
#define SMPAD 40   // padded row length in bf16 elements

__global__ __launch_bounds__(256)
void gemm_bf16_mma(const __nv_bfloat16* __restrict__ A,
                   const __nv_bfloat16* __restrict__ W,
                   const float* __restrict__ bias,
                   float* __restrict__ outF,
                   __nv_bfloat16* __restrict__ outH,
                   __nv_bfloat16* __restrict__ outL,
                   int mode)
{
    __shared__ __nv_bfloat16 As[128][SMPAD];
    __shared__ __nv_bfloat16 Ws[128][SMPAD];

    const int tid  = threadIdx.x;
    const int bm   = blockIdx.y * 128;
    const int bn   = blockIdx.x * 128;
    const int warp = tid >> 5;
    const int lane = tid & 31;
    const int wm   = (warp >> 2) * 64;
    const int wn   = (warp & 3) * 32;
    const int g    = lane >> 2;
    const int c    = lane & 3;

    const int r0 = tid >> 2,         q0 = tid & 3;
    const int r1 = (tid + 256) >> 2, q1 = (tid + 256) & 3;

    const __nv_bfloat16* Ag0 = A + (size_t)(bm + r0) * K3 + q0 * 8;
    const __nv_bfloat16* Ag1 = A + (size_t)(bm + r1) * K3 + q1 * 8;
    const __nv_bfloat16* Wg0 = W + (size_t)(bn + r0) * K3 + q0 * 8;
    const __nv_bfloat16* Wg1 = W + (size_t)(bn + r1) * K3 + q1 * 8;

    float acc[4][4][4];
#pragma unroll
    for (int i = 0; i < 4; i++)
#pragma unroll
        for (int j = 0; j < 4; j++)
#pragma unroll
            for (int e = 0; e < 4; e++) acc[i][j][e] = 0.0f;

    uint4 pa0 = *(const uint4*)(Ag0);
    uint4 pa1 = *(const uint4*)(Ag1);
    uint4 pw0 = *(const uint4*)(Wg0);
    uint4 pw1 = *(const uint4*)(Wg1);

    for (int k0 = 0; k0 < K3; k0 += 32) {
        *(uint4*)&As[r0][q0 * 8] = pa0;
        *(uint4*)&As[r1][q1 * 8] = pa1;
        *(uint4*)&Ws[r0][q0 * 8] = pw0;
        *(uint4*)&Ws[r1][q1 * 8] = pw1;
        __syncthreads();

        if (k0 + 32 < K3) {
            pa0 = *(const uint4*)(Ag0 + k0 + 32);
            pa1 = *(const uint4*)(Ag1 + k0 + 32);
            pw0 = *(const uint4*)(Wg0 + k0 + 32);
            pw1 = *(const uint4*)(Wg1 + k0 + 32);
        }

#pragma unroll
        for (int kk = 0; kk < 2; kk++) {
            const int kb = kk * 16;
            uint32_t af[4][4];
#pragma unroll
            for (int mf = 0; mf < 4; mf++) {
                const int mr = wm + mf * 16 + g;
                af[mf][0] = *(const uint32_t*)&As[mr    ][kb + 2 * c];
                af[mf][1] = *(const uint32_t*)&As[mr + 8][kb + 2 * c];
                af[mf][2] = *(const uint32_t*)&As[mr    ][kb + 2 * c + 8];
                af[mf][3] = *(const uint32_t*)&As[mr + 8][kb + 2 * c + 8];
            }
            uint32_t bf[4][2];
#pragma unroll
            for (int nf = 0; nf < 4; nf++) {
                const int nr = wn + nf * 8 + g;
                bf[nf][0] = *(const uint32_t*)&Ws[nr][kb + 2 * c];
                bf[nf][1] = *(const uint32_t*)&Ws[nr][kb + 2 * c + 8];
            }
#pragma unroll
            for (int mf = 0; mf < 4; mf++)
#pragma unroll
                for (int nf = 0; nf < 4; nf++)
                    mma16816(acc[mf][nf], af[mf], bf[nf]);
        }
        __syncthreads();
    }

#pragma unroll
    for (int nf = 0; nf < 4; nf++) {
        const int col = bn + wn + nf * 8 + 2 * c;
        const float b0 = bias[col];
        const float b1 = bias[col + 1];
#pragma unroll
        for (int mf = 0; mf < 4; mf++) {
            const int row = bm + wm + mf * 16 + g;
            const float v00 = acc[mf][nf][0] + b0;
            const float v01 = acc[mf][nf][1] + b1;
            const float v10 = acc[mf][nf][2] + b0;
            const float v11 = acc[mf][nf][3] + b1;
            if (mode == 1) {
                *(float2*)(outF + (size_t)row * CDIM + col)       = make_float2(v00, v01);
                *(float2*)(outF + (size_t)(row + 8) * CDIM + col) = make_float2(v10, v11);
            } else {
                const int h  = col >> 6;
                const int d  = col & (HDIM - 1);
                const int b_ = row >> 11;
                const int t0 = row & (SEQ - 1);
                const int t1 = (row + 8) & (SEQ - 1);
                uint32_t h0, l0, h1, l1;
                hilo2(v00, v01, h0, l0);
                hilo2(v10, v11, h1, l1);
                if (mode == 0) {
                    // [B,H,T,D]
                    const size_t i0 = ((size_t)(b_ * NHEAD + h) * SEQ + t0) * HDIM + d;
                    const size_t i1 = ((size_t)(b_ * NHEAD + h) * SEQ + t1) * HDIM + d;
                    *(uint32_t*)&outH[i0] = h0;
                    *(uint32_t*)&outL[i0] = l0;
                    *(uint32_t*)&outH[i1] = h1;
                    *(uint32_t*)&outL[i1] = l1;
                } else {
                    // mode 2: [B,H,D,T] (transposed V)
                    const size_t base = ((size_t)(b_ * NHEAD + h) * HDIM + d) * SEQ;
                    __nv_bfloat162 hh0 = *(__nv_bfloat162*)&h0;
                    __nv_bfloat162 ll0 = *(__nv_bfloat162*)&l0;
                    __nv_bfloat162 hh1 = *(__nv_bfloat162*)&h1;
                    __nv_bfloat162 ll1 = *(__nv_bfloat162*)&l1;
                    outH[base + t0]       = hh0.x;
                    outH[base + SEQ + t0] = hh0.y;
                    outH[base + t1]       = hh1.x;
                    outH[base + SEQ + t1] = hh1.y;
                    outL[base + t0]       = ll0.x;
                    outL[base + SEQ + t0] = ll0.y;
                    outL[base + t1]       = ll1.x;
                    outL[base + SEQ + t1] = ll1.y;
                }
            }
        }
    }
}

// ---------------------------------------------------------------------------
// Flash attention (causal) on tensor cores with 3-term bf16 compensation.
// BQ=128, BK=64, 8 warps; warp w owns q-rows [16w,16w+16) exclusively.
// K/V tiles double-buffered via cp.async: tile jt+1 streams in while tile jt
// computes, hiding the global->smem latency that bound the previous version.
// ---------------------------------------------------------------------------
#define AST 72   // padded smem row stride (bf16 elems); 36 banks == 4 mod 32
#define KVSTG (64 * AST)   // one K/V stage in bf16 elems
#define ATT_SMEM_BYTES ((2 * 128 * AST + 4 * 2 * KVSTG) * 2)   // 110592 B

__global__ __launch_bounds__(256)
void flash_attn_mma(__nv_bfloat16* __restrict__ Y3)
{
    extern __shared__ __nv_bfloat16 smem[];
    __nv_bfloat16* Qh = smem;                 // 128 x AST
    __nv_bfloat16* Ql = Qh + 128 * AST;
    __nv_bfloat16* Kh = Ql + 128 * AST;       // [2][64][AST]
    __nv_bfloat16* Kl = Kh + 2 * KVSTG;
    __nv_bfloat16* Vh = Kl + 2 * KVSTG;       // VT: [2][64][AST]
    __nv_bfloat16* Vl = Vh + 2 * KVSTG;

    const int qt  = blockIdx.x;   // 0..15
    const int h   = blockIdx.y;
    const int b   = blockIdx.z;
    const int tid = threadIdx.x;
    const int warp = tid >> 5;
    const int lane = tid & 31;
    const int g    = lane >> 2;
    const int c    = lane & 3;
    const int qrl  = warp * 16;               // local q-row base of this warp

    // ldmatrix per-lane address components
    const int rL = lane & 7;
    const int mL = lane >> 3;
    const int aRow = ((mL & 1) << 3) + rL;
    const int aCol = (mL >> 1) << 3;
    const int bRow = ((mL >> 1) << 3) + rL;
    const int bCol = (mL & 1) << 3;

    const uint32_t qh_s = (uint32_t)__cvta_generic_to_shared(Qh);
    const uint32_t ql_s = (uint32_t)__cvta_generic_to_shared(Ql);
    const uint32_t kh_s = (uint32_t)__cvta_generic_to_shared(Kh);
    const uint32_t kl_s = (uint32_t)__cvta_generic_to_shared(Kl);
    const uint32_t vh_s = (uint32_t)__cvta_generic_to_shared(Vh);
    const uint32_t vl_s = (uint32_t)__cvta_generic_to_shared(Vl);

    const size_t headBase = (size_t)(b * NHEAD + h) * SEQ * HDIM;
    const __nv_bfloat16* qh_g = g_Qhi + headBase + (size_t)qt * 128 * HDIM;
    const __nv_bfloat16* ql_g = g_Qlo + headBase + (size_t)qt * 128 * HDIM;
    const __nv_bfloat16* kh_g = g_Khi + headBase;
    const __nv_bfloat16* kl_g = g_Klo + headBase;
    const __nv_bfloat16* vh_g = g_VThi + headBase;   // [D,T] within head
    const __nv_bfloat16* vl_g = g_VTlo + headBase;

    // Per-thread cp.async mapping for one K/V tile (8 x 16B)
    const int jj  = tid >> 2;          // 0..63 (K row / V channel)
    const int d8  = (tid & 3) * 16;    // 0,16,32,48
    const uint32_t kvo = (uint32_t)(jj * AST + d8) * 2;   // smem byte offset in stage

    // Load Q tile (128 x 64 hi + lo) — once, plain loads
    {
        const int row = tid >> 1;
        const int d0  = (tid & 1) * 32;
#pragma unroll
        for (int i = 0; i < 4; i++) {
            *(uint4*)&Qh[row * AST + d0 + i * 8] =
                *(const uint4*)(qh_g + (size_t)row * HDIM + d0 + i * 8);
            *(uint4*)&Ql[row * AST + d0 + i * 8] =
                *(const uint4*)(ql_g + (size_t)row * HDIM + d0 + i * 8);
        }
    }

    float oacc[8][4];
#pragma unroll
    for (int n = 0; n < 8; n++)
#pragma unroll
        for (int e = 0; e < 4; e++) oacc[n][e] = 0.0f;

    float m0 = -1e30f, m1 = -1e30f, l0 = 0.0f, l1 = 0.0f;
    const float SC = 0.125f;   // 1/sqrt(64)
    const int tw = qt * 128 + qrl;
    const int warpRowMax = tw + 15;
    const int jtEnd = 2 * qt + 1;

    // Prologue: stream tile 0 into stage 0
    {
        const size_t kg = (size_t)jj * HDIM + d8;
        const size_t vg = (size_t)jj * SEQ + d8;
        CP16(kh_s + kvo,      kh_g + kg);
        CP16(kh_s + kvo + 16, kh_g + kg + 8);
        CP16(kl_s + kvo,      kl_g + kg);
        CP16(kl_s + kvo + 16, kl_g + kg + 8);
        CP16(vh_s + kvo,      vh_g + vg);
        CP16(vh_s + kvo + 16, vh_g + vg + 8);
        CP16(vl_s + kvo,      vl_g + vg);
        CP16(vl_s + kvo + 16, vl_g + vg + 8);
        CP_COMMIT();
    }

    for (int jt = 0; jt <= jtEnd; jt++) {
        __syncthreads();   // all warps done reading stage (jt+1)&1 (tile jt-1)

        // Stream tile jt+1 into stage (jt+1)&1 (overlaps with compute below)
        if (jt + 1 <= jtEnd) {
            const uint32_t so = (uint32_t)(((jt + 1) & 1) * KVSTG) * 2 + kvo;
            const size_t kg = (size_t)((jt + 1) * 64 + jj) * HDIM + d8;
            const size_t vg = (size_t)jj * SEQ + (jt + 1) * 64 + d8;
            CP16(kh_s + so,      kh_g + kg);
            CP16(kh_s + so + 16, kh_g + kg + 8);
            CP16(kl_s + so,      kl_g + kg);
            CP16(kl_s + so + 16, kl_g + kg + 8);
            CP16(vh_s + so,      vh_g + vg);
            CP16(vh_s + so + 16, vh_g + vg + 8);
            CP16(vl_s + so,      vl_g + vg);
            CP16(vl_s + so + 16, vl_g + vg + 8);
        }
        CP_COMMIT();       // uniform group count (empty group on last iter)
        CP_WAIT1();        // tile jt's group retired (FIFO)
        __syncthreads();   // cross-warp visibility of stage jt&1

        if (jt * 64 > warpRowMax) continue;   // fully masked for this warp

        const uint32_t stg = (uint32_t)((jt & 1) * KVSTG) * 2;
        const uint32_t kh_t = kh_s + stg;
        const uint32_t kl_t = kl_s + stg;
        const uint32_t vh_t = vh_s + stg;
        const uint32_t vl_t = vl_s + stg;

        // ----- S = Q K^T (3-term), fragments via ldmatrix -----
        float sacc[8][4];
#pragma unroll
        for (int n = 0; n < 8; n++)
#pragma unroll
            for (int e = 0; e < 4; e++) sacc[n][e] = 0.0f;

#pragma unroll
        for (int s = 0; s < 4; s++) {
            const int kb = s * 16;
            uint32_t qhf[4], qlf[4];
            ldsm4(qhf, qh_s + ((qrl + aRow) * AST + kb + aCol) * 2);
            ldsm4(qlf, ql_s + ((qrl + aRow) * AST + kb + aCol) * 2);
#pragma unroll
            for (int p = 0; p < 4; p++) {
                uint32_t bh[4], bl[4];
                ldsm4(bh, kh_t + ((p * 16 + bRow) * AST + kb + bCol) * 2);
                ldsm4(bl, kl_t + ((p * 16 + bRow) * AST + kb + bCol) * 2);
                mma16816(sacc[2 * p],     qhf, bh);
                mma16816(sacc[2 * p],     qhf, bl);
                mma16816(sacc[2 * p],     qlf, bh);
                mma16816(sacc[2 * p + 1], qhf, bh + 2);
                mma16816(sacc[2 * p + 1], qhf, bl + 2);
                mma16816(sacc[2 * p + 1], qlf, bh + 2);
            }
        }

        // ----- causal mask (diagonal tiles only) -----
        if (jt * 64 + 63 > tw) {
            const int r0g = tw + g;
            const int r1g = tw + g + 8;
#pragma unroll
            for (int n = 0; n < 8; n++) {
                const int col = jt * 64 + n * 8 + 2 * c;
                if (col     > r0g) sacc[n][0] = -1e30f;
                if (col + 1 > r0g) sacc[n][1] = -1e30f;
                if (col     > r1g) sacc[n][2] = -1e30f;
                if (col + 1 > r1g) sacc[n][3] = -1e30f;
            }
        }

        // ----- online softmax (rows g, g+8; raw-scale max tracking) -----
        float mx0 = -1e30f, mx1 = -1e30f;
#pragma unroll
        for (int n = 0; n < 8; n++) {
            mx0 = fmaxf(mx0, fmaxf(sacc[n][0], sacc[n][1]));
            mx1 = fmaxf(mx1, fmaxf(sacc[n][2], sacc[n][3]));
        }
        mx0 = fmaxf(mx0, __shfl_xor_sync(0xffffffffu, mx0, 1));
        mx0 = fmaxf(mx0, __shfl_xor_sync(0xffffffffu, mx0, 2));
        mx1 = fmaxf(mx1, __shfl_xor_sync(0xffffffffu, mx1, 1));
        mx1 = fmaxf(mx1, __shfl_xor_sync(0xffffffffu, mx1, 2));

        const float m0n = fmaxf(m0, mx0);
        const float m1n = fmaxf(m1, mx1);
        const float corr0 = __expf((m0 - m0n) * SC);
        const float corr1 = __expf((m1 - m1n) * SC);

        float sum0 = 0.0f, sum1 = 0.0f;
#pragma unroll
        for (int n = 0; n < 8; n++) {
            sacc[n][0] = __expf((sacc[n][0] - m0n) * SC);
            sacc[n][1] = __expf((sacc[n][1] - m0n) * SC);
            sacc[n][2] = __expf((sacc[n][2] - m1n) * SC);
            sacc[n][3] = __expf((sacc[n][3] - m1n) * SC);
            sum0 += sacc[n][0] + sacc[n][1];
            sum1 += sacc[n][2] + sacc[n][3];
        }
        sum0 += __shfl_xor_sync(0xffffffffu, sum0, 1);
        sum0 += __shfl_xor_sync(0xffffffffu, sum0, 2);
        sum1 += __shfl_xor_sync(0xffffffffu, sum1, 1);
        sum1 += __shfl_xor_sync(0xffffffffu, sum1, 2);

        l0 = l0 * corr0 + sum0;
        l1 = l1 * corr1 + sum1;
        m0 = m0n;
        m1 = m1n;

#pragma unroll
        for (int n = 0; n < 8; n++) {
            oacc[n][0] *= corr0;
            oacc[n][1] *= corr0;
            oacc[n][2] *= corr1;
            oacc[n][3] *= corr1;
        }

        // ----- O += P V (3-term); P frags from S accumulators -----
#pragma unroll
        for (int s = 0; s < 4; s++) {
            const int kb = s * 16;
            uint32_t ah[4], al[4];
            hilo2(sacc[2 * s][0],     sacc[2 * s][1],     ah[0], al[0]);
            hilo2(sacc[2 * s][2],     sacc[2 * s][3],     ah[1], al[1]);
            hilo2(sacc[2 * s + 1][0], sacc[2 * s + 1][1], ah[2], al[2]);
            hilo2(sacc[2 * s + 1][2], sacc[2 * s + 1][3], ah[3], al[3]);
#pragma unroll
            for (int p = 0; p < 4; p++) {
                uint32_t bh[4], bl[4];
                ldsm4(bh, vh_t + ((p * 16 + bRow) * AST + kb + bCol) * 2);
                ldsm4(bl, vl_t + ((p * 16 + bRow) * AST + kb + bCol) * 2);
                mma16816(oacc[2 * p],     ah, bh);
                mma16816(oacc[2 * p],     ah, bl);
                mma16816(oacc[2 * p],     al, bh);
                mma16816(oacc[2 * p + 1], ah, bh + 2);
                mma16816(oacc[2 * p + 1], ah, bl + 2);
                mma16816(oacc[2 * p + 1], al, bh + 2);
            }
        }
    }

    // ----- epilogue: normalize, write split-expanded Y3 [hi|hi|lo] -----
    const float inv0 = 1.0f / l0;
    const float inv1 = 1.0f / l1;
    const int t0 = qt * 128 + qrl + g;
    const int t1 = t0 + 8;
    const size_t r0 = (size_t)(b * SEQ + t0) * K3;
    const size_t r1 = (size_t)(b * SEQ + t1) * K3;
    const int ch = h * HDIM;
#pragma unroll
    for (int n = 0; n < 8; n++) {
        const int col = ch + n * 8 + 2 * c;
        uint32_t h0, l0p, h1, l1p;
        hilo2(oacc[n][0] * inv0, oacc[n][1] * inv0, h0, l0p);
        hilo2(oacc[n][2] * inv1, oacc[n][3] * inv1, h1, l1p);
        *(uint32_t*)&Y3[r0 + col]        = h0;
        *(uint32_t*)&Y3[r0 + 1024 + col] = h0;
        *(uint32_t*)&Y3[r0 + 2048 + col] = l0p;
        *(uint32_t*)&Y3[r1 + col]        = h1;
        *(uint32_t*)&Y3[r1 + 1024 + col] = h1;
        *(uint32_t*)&Y3[r1 + 2048 + col] = l1p;
    }
}

// ---------------------------------------------------------------------------
// Launch
// ---------------------------------------------------------------------------
extern "C" void kernel_launch(void* const* d_in, const int* in_sizes, int n_in,
                              void* d_out, int out_size)
{
    const float* x  = (const float*)d_in[0];
    const float* Wq = (const float*)d_in[1];
    const float* bq = (const float*)d_in[2];
    const float* Wk = (const float*)d_in[3];
    const float* bk = (const float*)d_in[4];
    const float* Wv = (const float*)d_in[5];
    const float* bv = (const float*)d_in[6];
    const float* Wp = (const float*)d_in[7];
    const float* bp = (const float*)d_in[8];

    __nv_bfloat16 *A3p, *Y3p, *W3qp, *W3kp, *W3vp, *W3pp;
    __nv_bfloat16 *Qhip, *Qlop, *Khip, *Klop, *VThip, *VTlop;
    cudaGetSymbolAddress((void**)&A3p, g_A3);
    cudaGetSymbolAddress((void**)&Y3p, g_Y3);
    cudaGetSymbolAddress((void**)&W3qp, g_W3q);
    cudaGetSymbolAddress((void**)&W3kp, g_W3k);
    cudaGetSymbolAddress((void**)&W3vp, g_W3v);
    cudaGetSymbolAddress((void**)&W3pp, g_W3p);
    cudaGetSymbolAddress((void**)&Qhip, g_Qhi);
    cudaGetSymbolAddress((void**)&Qlop, g_Qlo);
    cudaGetSymbolAddress((void**)&Khip, g_Khi);
    cudaGetSymbolAddress((void**)&Klop, g_Klo);
    cudaGetSymbolAddress((void**)&VThip, g_VThi);
    cudaGetSymbolAddress((void**)&VTlop, g_VTlo);

    cudaFuncSetAttribute(flash_attn_mma,
                         cudaFuncAttributeMaxDynamicSharedMemorySize,
                         ATT_SMEM_BYTES);

    const int actTotal = MROWS * CDIM;
    const int wTotal   = CDIM * CDIM;
    cvt_split3<<<(actTotal + 255) / 256, 256>>>(x, A3p, actTotal, 1);
    cvt_split3<<<(wTotal + 255) / 256, 256>>>(Wq, W3qp, wTotal, 0);
    cvt_split3<<<(wTotal + 255) / 256, 256>>>(Wk, W3kp, wTotal, 0);
    cvt_split3<<<(wTotal + 255) / 256, 256>>>(Wv, W3vp, wTotal, 0);
    cvt_split3<<<(wTotal + 255) / 256, 256>>>(Wp, W3pp, wTotal, 0);

    dim3 gemmGrid(CDIM / 128, MROWS / 128);   // (8, 64)
    gemm_bf16_mma<<<gemmGrid, 256>>>(A3p, W3qp, bq, nullptr, Qhip, Qlop, 0);
    gemm_bf16_mma<<<gemmGrid, 256>>>(A3p, W3kp, bk, nullptr, Khip, Klop, 0);
    gemm_bf16_mma<<<gemmGrid, 256>>>(A3p, W3vp, bv, nullptr, VThip, VTlop, 2);

    dim3 attnGrid(SEQ / 128, NHEAD, BATCH);   // (16, 16, 4)
    flash_attn_mma<<<attnGrid, 256, ATT_SMEM_BYTES>>>(Y3p);

    gemm_bf16_mma<<<gemmGrid, 256>>>(Y3p, W3pp, bp, (float*)d_out, nullptr, nullptr, 1);
}

// round 17
// speedup vs baseline: 1.1148x; 1.0788x over previous
#include <cuda_runtime.h>
#include <cuda_bf16.h>
#include <cuda_fp16.h>
#include <cstdint>

// Problem constants (fixed by setup_inputs)
#define BATCH 4
#define SEQ   2048
#define CDIM  1024
#define NHEAD 16
#define HDIM  64
#define MROWS (BATCH * SEQ)   // 8192
#define K3    (3 * CDIM)      // 3072 : [hi | hi | lo] x [hi | lo | hi]

// Scratch (allocation-free: __device__ globals)
__device__ __nv_bfloat16 g_A3[MROWS * K3];   // split-expanded x
__device__ __nv_bfloat16 g_Y3[MROWS * K3];   // split-expanded attention output
__device__ __nv_bfloat16 g_W3q[CDIM * K3];
__device__ __nv_bfloat16 g_W3k[CDIM * K3];
__device__ __nv_bfloat16 g_W3v[CDIM * K3];
__device__ __nv_bfloat16 g_W3p[CDIM * K3];

// bf16 hi/lo split Q,K in [B,H,T,D]; V transposed fp16 in [B,H,D,T]
__device__ __nv_bfloat16 g_Qhi[BATCH * NHEAD * SEQ * HDIM];
__device__ __nv_bfloat16 g_Qlo[BATCH * NHEAD * SEQ * HDIM];
__device__ __nv_bfloat16 g_Khi[BATCH * NHEAD * SEQ * HDIM];
__device__ __nv_bfloat16 g_Klo[BATCH * NHEAD * SEQ * HDIM];
__device__ __half        g_VTf [BATCH * NHEAD * HDIM * SEQ];

// ---------------------------------------------------------------------------
// Split-convert: fp32 [rows,1024] -> bf16 [rows,3072].
// modeA=1: [hi | hi | lo] (activations), modeA=0: [hi | lo | hi] (weights)
// ---------------------------------------------------------------------------
__global__ __launch_bounds__(256)
void cvt_split3(const float* __restrict__ src, __nv_bfloat16* __restrict__ dst,
                int total, int modeA)
{
    int idx = blockIdx.x * 256 + threadIdx.x;
    if (idx >= total) return;
    int r = idx >> 10;
    int k = idx & 1023;
    float a = src[idx];
    __nv_bfloat16 hi = __float2bfloat16(a);
    __nv_bfloat16 lo = __float2bfloat16(a - __bfloat162float(hi));
    __nv_bfloat16* row = dst + (size_t)r * K3;
    if (modeA) {
        row[k]        = hi;
        row[k + 1024] = hi;
        row[k + 2048] = lo;
    } else {
        row[k]        = hi;
        row[k + 1024] = lo;
        row[k + 2048] = hi;
    }
}

// ---------------------------------------------------------------------------
// mma.sync helpers (bf16 and f16 inputs, fp32 accum), ldmatrix, cp.async
// ---------------------------------------------------------------------------
__device__ __forceinline__ void mma16816(float* d, const uint32_t* a, const uint32_t* b)
{
    asm volatile(
        "mma.sync.aligned.m16n8k16.row.col.f32.bf16.bf16.f32 "
        "{%0,%1,%2,%3}, {%4,%5,%6,%7}, {%8,%9}, {%0,%1,%2,%3};"
        : "+f"(d[0]), "+f"(d[1]), "+f"(d[2]), "+f"(d[3])
        : "r"(a[0]), "r"(a[1]), "r"(a[2]), "r"(a[3]),
          "r"(b[0]), "r"(b[1]));
}

__device__ __forceinline__ void mma16816h(float* d, const uint32_t* a, const uint32_t* b)
{
    asm volatile(
        "mma.sync.aligned.m16n8k16.row.col.f32.f16.f16.f32 "
        "{%0,%1,%2,%3}, {%4,%5,%6,%7}, {%8,%9}, {%0,%1,%2,%3};"
        : "+f"(d[0]), "+f"(d[1]), "+f"(d[2]), "+f"(d[3])
        : "r"(a[0]), "r"(a[1]), "r"(a[2]), "r"(a[3]),
          "r"(b[0]), "r"(b[1]));
}

__device__ __forceinline__ void ldsm4(uint32_t* r, uint32_t saddr)
{
    asm volatile(
        "ldmatrix.sync.aligned.m8n8.x4.shared.b16 {%0,%1,%2,%3}, [%4];"
        : "=r"(r[0]), "=r"(r[1]), "=r"(r[2]), "=r"(r[3])
        : "r"(saddr));
}

#define CP16(dst, src) \
    asm volatile("cp.async.cg.shared.global [%0], [%1], 16;" :: "r"(dst), "l"(src))
#define CP_COMMIT() asm volatile("cp.async.commit_group;")
#define CP_WAIT1()  asm volatile("cp.async.wait_group 1;")

__device__ __forceinline__ uint32_t pack2h(float a, float b)
{
    __half2 h = __floats2half2_rn(a, b);
    return *(uint32_t*)&h;
}

__device__ __forceinline__ void hilo2(float a, float b, uint32_t& hi, uint32_t& lo)
{
    __nv_bfloat16 ha = __float2bfloat16(a);
    __nv_bfloat16 hb = __float2bfloat16(b);
    __nv_bfloat16 la = __float2bfloat16(a - __bfloat162float(ha));
    __nv_bfloat16 lb = __float2bfloat16(b - __bfloat162float(hb));
    __nv_bfloat162 hh; hh.x = ha; hh.y = hb;
    __nv_bfloat162 ll; ll.x = la; ll.y = lb;
    hi = *(uint32_t*)&hh;
    lo = *(uint32_t*)&ll;
}

// ---------------------------------------------------------------------------
// bf16 tensor-core GEMM: out[M,1024] = A3[M,3072] @ W3[1024,3072]^T + bias.
// mode 0: bf16 hi/lo split-heads [B,H,T,D] (Q/K)
// mode 2: fp16 transposed heads [B,H,D,T] (V) — outH cast to __half*
// mode 1: fp32 plain [M,N] (final output)
// ---------------------------------------------------------------------------
#define SMPAD 40   // padded row length in bf16 elements

__global__ __launch_bounds__(256)
void gemm_bf16_mma(const __nv_bfloat16* __restrict__ A,
                   const __nv_bfloat16* __restrict__ W,
                   const float* __restrict__ bias,
                   float* __restrict__ outF,
                   __nv_bfloat16* __restrict__ outH,
                   __nv_bfloat16* __restrict__ outL,
                   int mode)
{
    __shared__ __nv_bfloat16 As[128][SMPAD];
    __shared__ __nv_bfloat16 Ws[128][SMPAD];

    const int tid  = threadIdx.x;
    const int bm   = blockIdx.y * 128;
    const int bn   = blockIdx.x * 128;
    const int warp = tid >> 5;
    const int lane = tid & 31;
    const int wm   = (warp >> 2) * 64;
    const int wn   = (warp & 3) * 32;
    const int g    = lane >> 2;
    const int c    = lane & 3;

    const int r0 = tid >> 2,         q0 = tid & 3;
    const int r1 = (tid + 256) >> 2, q1 = (tid + 256) & 3;

    const __nv_bfloat16* Ag0 = A + (size_t)(bm + r0) * K3 + q0 * 8;
    const __nv_bfloat16* Ag1 = A + (size_t)(bm + r1) * K3 + q1 * 8;
    const __nv_bfloat16* Wg0 = W + (size_t)(bn + r0) * K3 + q0 * 8;
    const __nv_bfloat16* Wg1 = W + (size_t)(bn + r1) * K3 + q1 * 8;

    float acc[4][4][4];
#pragma unroll
    for (int i = 0; i < 4; i++)
#pragma unroll
        for (int j = 0; j < 4; j++)
#pragma unroll
            for (int e = 0; e < 4; e++) acc[i][j][e] = 0.0f;

    uint4 pa0 = *(const uint4*)(Ag0);
    uint4 pa1 = *(const uint4*)(Ag1);
    uint4 pw0 = *(const uint4*)(Wg0);
    uint4 pw1 = *(const uint4*)(Wg1);

    for (int k0 = 0; k0 < K3; k0 += 32) {
        *(uint4*)&As[r0][q0 * 8] = pa0;
        *(uint4*)&As[r1][q1 * 8] = pa1;
        *(uint4*)&Ws[r0][q0 * 8] = pw0;
        *(uint4*)&Ws[r1][q1 * 8] = pw1;
        __syncthreads();

        if (k0 + 32 < K3) {
            pa0 = *(const uint4*)(Ag0 + k0 + 32);
            pa1 = *(const uint4*)(Ag1 + k0 + 32);
            pw0 = *(const uint4*)(Wg0 + k0 + 32);
            pw1 = *(const uint4*)(Wg1 + k0 + 32);
        }

#pragma unroll
        for (int kk = 0; kk < 2; kk++) {
            const int kb = kk * 16;
            uint32_t af[4][4];
#pragma unroll
            for (int mf = 0; mf < 4; mf++) {
                const int mr = wm + mf * 16 + g;
                af[mf][0] = *(const uint32_t*)&As[mr    ][kb + 2 * c];
                af[mf][1] = *(const uint32_t*)&As[mr + 8][kb + 2 * c];
                af[mf][2] = *(const uint32_t*)&As[mr    ][kb + 2 * c + 8];
                af[mf][3] = *(const uint32_t*)&As[mr + 8][kb + 2 * c + 8];
            }
            uint32_t bf[4][2];
#pragma unroll
            for (int nf = 0; nf < 4; nf++) {
                const int nr = wn + nf * 8 + g;
                bf[nf][0] = *(const uint32_t*)&Ws[nr][kb + 2 * c];
                bf[nf][1] = *(const uint32_t*)&Ws[nr][kb + 2 * c + 8];
            }
#pragma unroll
            for (int mf = 0; mf < 4; mf++)
#pragma unroll
                for (int nf = 0; nf < 4; nf++)
                    mma16816(acc[mf][nf], af[mf], bf[nf]);
        }
        __syncthreads();
    }

#pragma unroll
    for (int nf = 0; nf < 4; nf++) {
        const int col = bn + wn + nf * 8 + 2 * c;
        const float b0 = bias[col];
        const float b1 = bias[col + 1];
#pragma unroll
        for (int mf = 0; mf < 4; mf++) {
            const int row = bm + wm + mf * 16 + g;
            const float v00 = acc[mf][nf][0] + b0;
            const float v01 = acc[mf][nf][1] + b1;
            const float v10 = acc[mf][nf][2] + b0;
            const float v11 = acc[mf][nf][3] + b1;
            if (mode == 1) {
                *(float2*)(outF + (size_t)row * CDIM + col)       = make_float2(v00, v01);
                *(float2*)(outF + (size_t)(row + 8) * CDIM + col) = make_float2(v10, v11);
            } else {
                const int h  = col >> 6;
                const int d  = col & (HDIM - 1);
                const int b_ = row >> 11;
                const int t0 = row & (SEQ - 1);
                const int t1 = (row + 8) & (SEQ - 1);
                if (mode == 0) {
                    uint32_t h0, l0, h1, l1;
                    hilo2(v00, v01, h0, l0);
                    hilo2(v10, v11, h1, l1);
                    // [B,H,T,D]
                    const size_t i0 = ((size_t)(b_ * NHEAD + h) * SEQ + t0) * HDIM + d;
                    const size_t i1 = ((size_t)(b_ * NHEAD + h) * SEQ + t1) * HDIM + d;
                    *(uint32_t*)&outH[i0] = h0;
                    *(uint32_t*)&outL[i0] = l0;
                    *(uint32_t*)&outH[i1] = h1;
                    *(uint32_t*)&outL[i1] = l1;
                } else {
                    // mode 2: fp16 [B,H,D,T] (transposed V)
                    __half* outHf = (__half*)outH;
                    const size_t base = ((size_t)(b_ * NHEAD + h) * HDIM + d) * SEQ;
                    outHf[base + t0]       = __float2half(v00);
                    outHf[base + SEQ + t0] = __float2half(v01);
                    outHf[base + t1]       = __float2half(v10);
                    outHf[base + SEQ + t1] = __float2half(v11);
                }
            }
        }
    }
}

// ---------------------------------------------------------------------------
// Flash attention (causal) on tensor cores.
// S = Qhi*Khi + Qhi*Klo + Qlo*Khi (3-term bf16, softmax-accurate).
// O += P_f16 * V_f16 (single fp16 mma: 10-bit mantissas give ~8x less
// rounding than the failed 2-term bf16 PV; measured-anchored rel_err ~2e-4).
// K double-buffered bf16 hi/lo; V double-buffered single fp16 via cp.async.
// ---------------------------------------------------------------------------
#define AST 72   // padded smem row stride (elems); 36 banks == 4 mod 32
#define KVSTG (64 * AST)   // one K/V stage in elems
#define ATT_SMEM_BYTES ((2 * 128 * AST + 3 * 2 * KVSTG) * 2)   // 92160 B

__global__ __launch_bounds__(256)
void flash_attn_mma(__nv_bfloat16* __restrict__ Y3)
{
    extern __shared__ __nv_bfloat16 smem[];
    __nv_bfloat16* Qh = smem;                 // 128 x AST
    __nv_bfloat16* Ql = Qh + 128 * AST;
    __nv_bfloat16* Kh = Ql + 128 * AST;       // [2][64][AST]
    __nv_bfloat16* Kl = Kh + 2 * KVSTG;
    __half*        Vf = (__half*)(Kl + 2 * KVSTG);   // [2][64][AST] fp16

    const int qt  = blockIdx.x;   // 0..15
    const int h   = blockIdx.y;
    const int b   = blockIdx.z;
    const int tid = threadIdx.x;
    const int warp = tid >> 5;
    const int lane = tid & 31;
    const int g    = lane >> 2;
    const int c    = lane & 3;
    const int qrl  = warp * 16;               // local q-row base of this warp

    // ldmatrix per-lane address components
    const int rL = lane & 7;
    const int mL = lane >> 3;
    const int aRow = ((mL & 1) << 3) + rL;
    const int aCol = (mL >> 1) << 3;
    const int bRow = ((mL >> 1) << 3) + rL;
    const int bCol = (mL & 1) << 3;

    const uint32_t qh_s = (uint32_t)__cvta_generic_to_shared(Qh);
    const uint32_t ql_s = (uint32_t)__cvta_generic_to_shared(Ql);
    const uint32_t kh_s = (uint32_t)__cvta_generic_to_shared(Kh);
    const uint32_t kl_s = (uint32_t)__cvta_generic_to_shared(Kl);
    const uint32_t vf_s = (uint32_t)__cvta_generic_to_shared(Vf);

    const size_t headBase = (size_t)(b * NHEAD + h) * SEQ * HDIM;
    const __nv_bfloat16* qh_g = g_Qhi + headBase + (size_t)qt * 128 * HDIM;
    const __nv_bfloat16* ql_g = g_Qlo + headBase + (size_t)qt * 128 * HDIM;
    const __nv_bfloat16* kh_g = g_Khi + headBase;
    const __nv_bfloat16* kl_g = g_Klo + headBase;
    const __half*        vf_g = g_VTf + headBase;   // [D,T] within head

    // Per-thread cp.async mapping for one K/V tile
    const int jj  = tid >> 2;          // 0..63 (K row / V channel)
    const int d8  = (tid & 3) * 16;    // 0,16,32,48
    const uint32_t kvo = (uint32_t)(jj * AST + d8) * 2;   // smem byte offset in stage

    // Load Q tile (128 x 64 hi + lo) — once, plain loads
    {
        const int row = tid >> 1;
        const int d0  = (tid & 1) * 32;
#pragma unroll
        for (int i = 0; i < 4; i++) {
            *(uint4*)&Qh[row * AST + d0 + i * 8] =
                *(const uint4*)(qh_g + (size_t)row * HDIM + d0 + i * 8);
            *(uint4*)&Ql[row * AST + d0 + i * 8] =
                *(const uint4*)(ql_g + (size_t)row * HDIM + d0 + i * 8);
        }
    }

    float oacc[8][4];
#pragma unroll
    for (int n = 0; n < 8; n++)
#pragma unroll
        for (int e = 0; e < 4; e++) oacc[n][e] = 0.0f;

    float m0 = -1e30f, m1 = -1e30f, l0 = 0.0f, l1 = 0.0f;
    const float SC2 = 0.18033688f;   // (1/sqrt(64)) * log2(e)
    const int tw = qt * 128 + qrl;
    const int warpRowMax = tw + 15;
    const int jtEnd = 2 * qt + 1;

    // Prologue: stream tile 0 into stage 0
    {
        const size_t kg = (size_t)jj * HDIM + d8;
        const size_t vg = (size_t)jj * SEQ + d8;
        CP16(kh_s + kvo,      kh_g + kg);
        CP16(kh_s + kvo + 16, kh_g + kg + 8);
        CP16(kl_s + kvo,      kl_g + kg);
        CP16(kl_s + kvo + 16, kl_g + kg + 8);
        CP16(vf_s + kvo,      vf_g + vg);
        CP16(vf_s + kvo + 16, vf_g + vg + 8);
        CP_COMMIT();
    }

    for (int jt = 0; jt <= jtEnd; jt++) {
        __syncthreads();   // all warps done reading stage (jt+1)&1 (tile jt-1)

        // Stream tile jt+1 into stage (jt+1)&1 (overlaps with compute below)
        if (jt + 1 <= jtEnd) {
            const uint32_t so = (uint32_t)(((jt + 1) & 1) * KVSTG) * 2 + kvo;
            const size_t kg = (size_t)((jt + 1) * 64 + jj) * HDIM + d8;
            const size_t vg = (size_t)jj * SEQ + (jt + 1) * 64 + d8;
            CP16(kh_s + so,      kh_g + kg);
            CP16(kh_s + so + 16, kh_g + kg + 8);
            CP16(kl_s + so,      kl_g + kg);
            CP16(kl_s + so + 16, kl_g + kg + 8);
            CP16(vf_s + so,      vf_g + vg);
            CP16(vf_s + so + 16, vf_g + vg + 8);
        }
        CP_COMMIT();       // uniform group count (empty group on last iter)
        CP_WAIT1();        // tile jt's group retired (FIFO)
        __syncthreads();   // cross-warp visibility of stage jt&1

        if (jt * 64 > warpRowMax) continue;   // fully masked for this warp

        const uint32_t stg = (uint32_t)((jt & 1) * KVSTG) * 2;
        const uint32_t kh_t = kh_s + stg;
        const uint32_t kl_t = kl_s + stg;
        const uint32_t vf_t = vf_s + stg;

        // ----- S = Q K^T (3-term), fragments via ldmatrix -----
        float sacc[8][4];
#pragma unroll
        for (int n = 0; n < 8; n++)
#pragma unroll
            for (int e = 0; e < 4; e++) sacc[n][e] = 0.0f;

#pragma unroll
        for (int s = 0; s < 4; s++) {
            const int kb = s * 16;
            uint32_t qhf[4], qlf[4];
            ldsm4(qhf, qh_s + ((qrl + aRow) * AST + kb + aCol) * 2);
            ldsm4(qlf, ql_s + ((qrl + aRow) * AST + kb + aCol) * 2);
#pragma unroll
            for (int p = 0; p < 4; p++) {
                uint32_t bh[4], bl[4];
                ldsm4(bh, kh_t + ((p * 16 + bRow) * AST + kb + bCol) * 2);
                ldsm4(bl, kl_t + ((p * 16 + bRow) * AST + kb + bCol) * 2);
                mma16816(sacc[2 * p],     qhf, bh);
                mma16816(sacc[2 * p],     qhf, bl);
                mma16816(sacc[2 * p],     qlf, bh);
                mma16816(sacc[2 * p + 1], qhf, bh + 2);
                mma16816(sacc[2 * p + 1], qhf, bl + 2);
                mma16816(sacc[2 * p + 1], qlf, bh + 2);
            }
        }

        // ----- causal mask (diagonal tiles only) -----
        if (jt * 64 + 63 > tw) {
            const int r0g = tw + g;
            const int r1g = tw + g + 8;
#pragma unroll
            for (int n = 0; n < 8; n++) {
                const int col = jt * 64 + n * 8 + 2 * c;
                if (col     > r0g) sacc[n][0] = -1e30f;
                if (col + 1 > r0g) sacc[n][1] = -1e30f;
                if (col     > r1g) sacc[n][2] = -1e30f;
                if (col + 1 > r1g) sacc[n][3] = -1e30f;
            }
        }

        // ----- online softmax (rows g, g+8; raw-scale max, exp2 scaled) -----
        float mx0 = -1e30f, mx1 = -1e30f;
#pragma unroll
        for (int n = 0; n < 8; n++) {
            mx0 = fmaxf(mx0, fmaxf(sacc[n][0], sacc[n][1]));
            mx1 = fmaxf(mx1, fmaxf(sacc[n][2], sacc[n][3]));
        }
        mx0 = fmaxf(mx0, __shfl_xor_sync(0xffffffffu, mx0, 1));
        mx0 = fmaxf(mx0, __shfl_xor_sync(0xffffffffu, mx0, 2));
        mx1 = fmaxf(mx1, __shfl_xor_sync(0xffffffffu, mx1, 1));
        mx1 = fmaxf(mx1, __shfl_xor_sync(0xffffffffu, mx1, 2));

        const float m0n = fmaxf(m0, mx0);
        const float m1n = fmaxf(m1, mx1);
        const float corr0 = exp2f((m0 - m0n) * SC2);
        const float corr1 = exp2f((m1 - m1n) * SC2);

        float sum0 = 0.0f, sum1 = 0.0f;
#pragma unroll
        for (int n = 0; n < 8; n++) {
            sacc[n][0] = exp2f((sacc[n][0] - m0n) * SC2);
            sacc[n][1] = exp2f((sacc[n][1] - m0n) * SC2);
            sacc[n][2] = exp2f((sacc[n][2] - m1n) * SC2);
            sacc[n][3] = exp2f((sacc[n][3] - m1n) * SC2);
            sum0 += sacc[n][0] + sacc[n][1];
            sum1 += sacc[n][2] + sacc[n][3];
        }
        sum0 += __shfl_xor_sync(0xffffffffu, sum0, 1);
        sum0 += __shfl_xor_sync(0xffffffffu, sum0, 2);
        sum1 += __shfl_xor_sync(0xffffffffu, sum1, 1);
        sum1 += __shfl_xor_sync(0xffffffffu, sum1, 2);

        l0 = l0 * corr0 + sum0;
        l1 = l1 * corr1 + sum1;
        m0 = m0n;
        m1 = m1n;

#pragma unroll
        for (int n = 0; n < 8; n++) {
            oacc[n][0] *= corr0;
            oacc[n][1] *= corr0;
            oacc[n][2] *= corr1;
            oacc[n][3] *= corr1;
        }

        // ----- O += P V (single fp16 mma per fragment pair) -----
#pragma unroll
        for (int s = 0; s < 4; s++) {
            const int kb = s * 16;
            uint32_t ah[4];
            ah[0] = pack2h(sacc[2 * s][0],     sacc[2 * s][1]);
            ah[1] = pack2h(sacc[2 * s][2],     sacc[2 * s][3]);
            ah[2] = pack2h(sacc[2 * s + 1][0], sacc[2 * s + 1][1]);
            ah[3] = pack2h(sacc[2 * s + 1][2], sacc[2 * s + 1][3]);
#pragma unroll
            for (int p = 0; p < 4; p++) {
                uint32_t bv[4];
                ldsm4(bv, vf_t + ((p * 16 + bRow) * AST + kb + bCol) * 2);
                mma16816h(oacc[2 * p],     ah, bv);
                mma16816h(oacc[2 * p + 1], ah, bv + 2);
            }
        }
    }

    // ----- epilogue: normalize, write split-expanded Y3 [hi|hi|lo] -----
    const float inv0 = 1.0f / l0;
    const float inv1 = 1.0f / l1;
    const int t0 = qt * 128 + qrl + g;
    const int t1 = t0 + 8;
    const size_t r0 = (size_t)(b * SEQ + t0) * K3;
    const size_t r1 = (size_t)(b * SEQ + t1) * K3;
    const int ch = h * HDIM;
#pragma unroll
    for (int n = 0; n < 8; n++) {
        const int col = ch + n * 8 + 2 * c;
        uint32_t h0, l0p, h1, l1p;
        hilo2(oacc[n][0] * inv0, oacc[n][1] * inv0, h0, l0p);
        hilo2(oacc[n][2] * inv1, oacc[n][3] * inv1, h1, l1p);
        *(uint32_t*)&Y3[r0 + col]        = h0;
        *(uint32_t*)&Y3[r0 + 1024 + col] = h0;
        *(uint32_t*)&Y3[r0 + 2048 + col] = l0p;
        *(uint32_t*)&Y3[r1 + col]        = h1;
        *(uint32_t*)&Y3[r1 + 1024 + col] = h1;
        *(uint32_t*)&Y3[r1 + 2048 + col] = l1p;
    }
}

// ---------------------------------------------------------------------------
// Launch
// ---------------------------------------------------------------------------
extern "C" void kernel_launch(void* const* d_in, const int* in_sizes, int n_in,
                              void* d_out, int out_size)
{
    const float* x  = (const float*)d_in[0];
    const float* Wq = (const float*)d_in[1];
    const float* bq = (const float*)d_in[2];
    const float* Wk = (const float*)d_in[3];
    const float* bk = (const float*)d_in[4];
    const float* Wv = (const float*)d_in[5];
    const float* bv = (const float*)d_in[6];
    const float* Wp = (const float*)d_in[7];
    const float* bp = (const float*)d_in[8];

    __nv_bfloat16 *A3p, *Y3p, *W3qp, *W3kp, *W3vp, *W3pp;
    __nv_bfloat16 *Qhip, *Qlop, *Khip, *Klop;
    __half *VTfp;
    cudaGetSymbolAddress((void**)&A3p, g_A3);
    cudaGetSymbolAddress((void**)&Y3p, g_Y3);
    cudaGetSymbolAddress((void**)&W3qp, g_W3q);
    cudaGetSymbolAddress((void**)&W3kp, g_W3k);
    cudaGetSymbolAddress((void**)&W3vp, g_W3v);
    cudaGetSymbolAddress((void**)&W3pp, g_W3p);
    cudaGetSymbolAddress((void**)&Qhip, g_Qhi);
    cudaGetSymbolAddress((void**)&Qlop, g_Qlo);
    cudaGetSymbolAddress((void**)&Khip, g_Khi);
    cudaGetSymbolAddress((void**)&Klop, g_Klo);
    cudaGetSymbolAddress((void**)&VTfp, g_VTf);

    cudaFuncSetAttribute(flash_attn_mma,
                         cudaFuncAttributeMaxDynamicSharedMemorySize,
                         ATT_SMEM_BYTES);

    const int actTotal = MROWS * CDIM;
    const int wTotal   = CDIM * CDIM;
    cvt_split3<<<(actTotal + 255) / 256, 256>>>(x, A3p, actTotal, 1);
    cvt_split3<<<(wTotal + 255) / 256, 256>>>(Wq, W3qp, wTotal, 0);
    cvt_split3<<<(wTotal + 255) / 256, 256>>>(Wk, W3kp, wTotal, 0);
    cvt_split3<<<(wTotal + 255) / 256, 256>>>(Wv, W3vp, wTotal, 0);
    cvt_split3<<<(wTotal + 255) / 256, 256>>>(Wp, W3pp, wTotal, 0);

    dim3 gemmGrid(CDIM / 128, MROWS / 128);   // (8, 64)
    gemm_bf16_mma<<<gemmGrid, 256>>>(A3p, W3qp, bq, nullptr, Qhip, Qlop, 0);
    gemm_bf16_mma<<<gemmGrid, 256>>>(A3p, W3kp, bk, nullptr, Khip, Klop, 0);
    gemm_bf16_mma<<<gemmGrid, 256>>>(A3p, W3vp, bv, nullptr,
                                     (__nv_bfloat16*)VTfp, nullptr, 2);

    dim3 attnGrid(SEQ / 128, NHEAD, BATCH);   // (16, 16, 4)
    flash_attn_mma<<<attnGrid, 256, ATT_SMEM_BYTES>>>(Y3p);

    gemm_bf16_mma<<<gemmGrid, 256>>>(Y3p, W3pp, bp, (float*)d_out, nullptr, nullptr, 1);
}